// round 12
// baseline (speedup 1.0000x reference)
#include <cuda_runtime.h>
#include <cstdint>

#define NE    8192
#define DIM   128
#define PMAX  5
#define NNODE 512
#define TOTAL (NNODE * NNODE)

#define DOT_CTAS     256
#define DOT_THREADS  256
#define EDGES_DCTA   32                        // edges per dot CTA (8 warps x 4)
#define G_CTAS       128
#define THREADS      1024
#define PAIRS_CTA    (TOTAL / G_CTAS)          // 2048
#define TBL_BYTES    (NE * PMAX * 4)           // 163840, layout [e][p]
#define NCHUNK       8
#define CHUNK_EDGES  (NE / NCHUNK)             // 1024
#define CHUNK_BYTES  (CHUNK_EDGES * PMAX * 4)  // 20480
#define DCTA_PER_CHUNK (CHUNK_EDGES / EDGES_DCTA) // 32
#define PATH_BYTES   (PAIRS_CTA * PMAX * 4)    // 40960
#define SMEM_BYTES   (TBL_BYTES + PATH_BYTES)  // 204800

// Precomputed dot products, layout [e][p] (20B per edge row) so completion is
// contiguous per edge range -> chunked fill can overlap the dot kernel.
__device__ float g_dots[NE * PMAX];
// Monotone counters (never reset -> graph-replay safe).
__device__ unsigned int g_done[NCHUNK];   // +DCTA_PER_CHUNK per replay each
__device__ unsigned int g_gen = 0;        // +G_CTAS per replay

__device__ __forceinline__ uint32_t smem_u32(const void* p) {
    return (uint32_t)__cvta_generic_to_shared(p);
}

__device__ __forceinline__ void mbar_init(uint32_t mb) {
    asm volatile("mbarrier.init.shared.b64 [%0], 1;" :: "r"(mb));
}

__device__ __forceinline__ void mbar_wait(uint32_t mb) {
    uint32_t done;
    asm volatile(
        "{\n\t.reg .pred p;\n\t"
        "mbarrier.try_wait.parity.acquire.cta.shared::cta.b64 p, [%1], 0;\n\t"
        "selp.b32 %0, 1, 0, p;\n\t}"
        : "=r"(done) : "r"(mb) : "memory");
    while (!done) {
        asm volatile(
            "{\n\t.reg .pred p;\n\t"
            "mbarrier.try_wait.parity.acquire.cta.shared::cta.b64 p, [%1], 0, 0x989680;\n\t"
            "selp.b32 %0, 1, 0, p;\n\t}"
            : "=r"(done) : "r"(mb) : "memory");
    }
}

__device__ __forceinline__ void bulk_copy(uint32_t dst, const void* src,
                                          uint32_t bytes, uint32_t mb) {
    asm volatile(
        "cp.async.bulk.shared::cta.global.mbarrier::complete_tx::bytes "
        "[%0], [%1], %2, [%3];"
        :: "r"(dst), "l"(src), "r"(bytes), "r"(mb) : "memory");
}

// ---------------------------------------------------------------------------
// Kernel 1 (PDL primary): dots[e][p] = sum_d emb[e][d] * ev[p][d]
// 256 CTAs x 256 threads, warp -> 4 edges. CTA b covers edges [32b, 32b+32):
// on completion it bumps its chunk counter so the gather can fill that chunk.
// ---------------------------------------------------------------------------
__global__ __launch_bounds__(DOT_THREADS, 2) void edge_dot_kernel(
        const float* __restrict__ emb, const float* __restrict__ ev) {
    asm volatile("griddepcontrol.launch_dependents;" ::: "memory");

    const int lane = threadIdx.x & 31;
    const int w    = threadIdx.x >> 5;                 // 0..7
    const int eb   = (blockIdx.x * 8 + w) * 4;

    float4 evr[PMAX];
#pragma unroll
    for (int p = 0; p < PMAX; ++p)
        evr[p] = __ldg(((const float4*)ev) + p * (DIM / 4) + lane);

#pragma unroll
    for (int g = 0; g < 2; ++g) {
        const int e0 = eb + g * 2;
        float4 a0 = __ldg(((const float4*)emb) + (e0    ) * (DIM / 4) + lane);
        float4 a1 = __ldg(((const float4*)emb) + (e0 + 1) * (DIM / 4) + lane);

        float pa[PMAX], pb[PMAX];
#pragma unroll
        for (int p = 0; p < PMAX; ++p) {
            pa[p] = a0.x * evr[p].x + a0.y * evr[p].y + a0.z * evr[p].z + a0.w * evr[p].w;
            pb[p] = a1.x * evr[p].x + a1.y * evr[p].y + a1.z * evr[p].z + a1.w * evr[p].w;
        }
#pragma unroll
        for (int off = 16; off > 0; off >>= 1) {
#pragma unroll
            for (int p = 0; p < PMAX; ++p) {
                pa[p] += __shfl_xor_sync(0xffffffffu, pa[p], off);
                pb[p] += __shfl_xor_sync(0xffffffffu, pb[p], off);
            }
        }
        if (lane == 0) {
#pragma unroll
            for (int p = 0; p < PMAX; ++p) {
                g_dots[e0 * PMAX + p]       = pa[p];
                g_dots[(e0 + 1) * PMAX + p] = pb[p];
            }
        }
    }

    if (lane == 0) __threadfence();           // flush this warp's STGs
    __syncthreads();
    if (threadIdx.x == 0)
        atomicAdd(&g_done[blockIdx.x / DCTA_PER_CHUNK], 1u);
}

// ---------------------------------------------------------------------------
// Kernel 2 (PDL secondary): 128 CTAs x 1024 threads x 2 pairs = 262144.
// Paths TMA + index reads overlap the dot kernel; table chunks are TMA'd as
// soon as their producing dot CTAs retire (8 x 20KB, progressive).
// ---------------------------------------------------------------------------
__global__ __launch_bounds__(THREADS, 1) void gather_kernel(
        const int* __restrict__ paths, float* __restrict__ out) {
    extern __shared__ __align__(16) char smem[];
    float* s_dots  = (float*)smem;                 // 163840 B, [e][p]
    int*   s_paths = (int*)(smem + TBL_BYTES);     // 40960 B
    __shared__ __align__(8) unsigned long long mbars[NCHUNK + 1];

    const int tid = threadIdx.x;
    uint32_t mbc[NCHUNK];
#pragma unroll
    for (int c = 0; c < NCHUNK; ++c) mbc[c] = smem_u32(&mbars[c]);
    const uint32_t mbp = smem_u32(&mbars[NCHUNK]);

    if (tid == 0) {
#pragma unroll
        for (int i = 0; i < NCHUNK + 1; ++i) mbar_init(smem_u32(&mbars[i]));
        asm volatile("fence.proxy.async.shared::cta;" ::: "memory");
        // paths slice: independent of dots -> overlaps the dot kernel
        asm volatile("mbarrier.arrive.expect_tx.shared.b64 _, [%0], %1;"
                     :: "r"(mbp), "r"((uint32_t)PATH_BYTES) : "memory");
        bulk_copy(smem_u32(s_paths),
                  (const char*)paths + blockIdx.x * PATH_BYTES,
                  PATH_BYTES, mbp);
    }
    __syncthreads();

    if (tid == 0) {
        // epoch from monotone generation counter (graph-replay safe)
        unsigned int t = atomicAdd(&g_gen, 1u);
        unsigned int epoch = t / G_CTAS;

        // progressive chunk fill: spin each chunk's counter, then TMA it
#pragma unroll
        for (int c = 0; c < NCHUNK; ++c) {
            unsigned int target = (epoch + 1u) * DCTA_PER_CHUNK;
            volatile unsigned int* vd = &g_done[c];
            while (*vd < target) { }
            __threadfence();                              // acquire
            asm volatile("fence.proxy.async.global;" ::: "memory");
            asm volatile("mbarrier.arrive.expect_tx.shared.b64 _, [%0], %1;"
                         :: "r"(mbc[c]), "r"((uint32_t)CHUNK_BYTES) : "memory");
            bulk_copy(smem_u32(s_dots) + c * CHUNK_BYTES,
                      (const char*)g_dots + c * CHUNK_BYTES,
                      CHUNK_BYTES, mbc[c]);
        }
    }

    // --- indices: thread t -> pairs t and t+1024; stride-5 = conflict-free
    //     (runs during tid0's spins: overlaps the dot kernel)
    mbar_wait(mbp);
    int e0[PMAX], e1[PMAX];
#pragma unroll
    for (int p = 0; p < PMAX; ++p) e0[p] = s_paths[5 * tid + p];
#pragma unroll
    for (int p = 0; p < PMAX; ++p) e1[p] = s_paths[5 * (tid + 1024) + p];

    int c0 = 0, c1 = 0;
#pragma unroll
    for (int p = 0; p < PMAX; ++p) { if (e0[p] >= 0) ++c0; if (e1[p] >= 0) ++c1; }

    // --- wait for the full table (last chunks land right after dot ends) ---
#pragma unroll
    for (int c = 0; c < NCHUNK; ++c) mbar_wait(mbc[c]);

    // --- gather + reduce, layout [e][p] ---
    float a0 = 0.f, a1 = 0.f;
#pragma unroll
    for (int p = 0; p < PMAX; ++p) {
        if (e0[p] >= 0) a0 += s_dots[e0[p] * PMAX + p];
        if (e1[p] >= 0) a1 += s_dots[e1[p] * PMAX + p];
    }

    float* ob = out + blockIdx.x * PAIRS_CTA;
    ob[tid]        = c0 ? a0 / (float)c0 : 0.0f;
    ob[tid + 1024] = c1 ? a1 / (float)c1 : 0.0f;
}

// ---------------------------------------------------------------------------
// Launch: primary + PDL secondary.
// ---------------------------------------------------------------------------
extern "C" void kernel_launch(void* const* d_in, const int* in_sizes, int n_in,
                              void* d_out, int out_size) {
    const float* emb   = nullptr;
    const int*   paths = nullptr;
    const float* ev    = nullptr;
    for (int i = 0; i < n_in; ++i) {
        if (in_sizes[i] == NE * DIM)                  emb   = (const float*)d_in[i];
        else if (in_sizes[i] == NNODE * NNODE * PMAX) paths = (const int*)d_in[i];
        else if (in_sizes[i] == PMAX * DIM)           ev    = (const float*)d_in[i];
    }
    float* out = (float*)d_out;

    cudaFuncSetAttribute(edge_dot_kernel,
                         cudaFuncAttributePreferredSharedMemoryCarveout, 100);
    cudaFuncSetAttribute(gather_kernel,
                         cudaFuncAttributeMaxDynamicSharedMemorySize,
                         SMEM_BYTES);

    edge_dot_kernel<<<DOT_CTAS, DOT_THREADS>>>(emb, ev);

    cudaLaunchConfig_t cfg = {};
    cfg.gridDim          = dim3(G_CTAS, 1, 1);
    cfg.blockDim         = dim3(THREADS, 1, 1);
    cfg.dynamicSmemBytes = SMEM_BYTES;
    cudaLaunchAttribute attr[1];
    attr[0].id = cudaLaunchAttributeProgrammaticStreamSerialization;
    attr[0].val.programmaticStreamSerializationAllowed = 1;
    cfg.attrs    = attr;
    cfg.numAttrs = 1;
    cudaLaunchKernelEx(&cfg, gather_kernel, paths, out);
}

// round 13
// speedup vs baseline: 1.3499x; 1.3499x over previous
#include <cuda_runtime.h>
#include <cstdint>

#define NE    8192
#define DIM   128
#define PMAX  5
#define NNODE 512
#define TOTAL (NNODE * NNODE)

#define G_CTAS       128
#define THREADS      1024
#define PAIRS_CTA    (TOTAL / G_CTAS)          // 2048
#define TBL_BYTES    (PMAX * NE * 4)           // 163840, layout [p][e]
#define CHUNK_BYTES  (NE * 4)                  // 32768 (one p slice)
#define PATH_BYTES   (PAIRS_CTA * PMAX * 4)    // 40960
#define SMEM_BYTES   (TBL_BYTES + PATH_BYTES)  // 204800

// Precomputed dot products, layout [p][e].
__device__ float g_dots[PMAX * NE];

__device__ __forceinline__ uint32_t smem_u32(const void* p) {
    return (uint32_t)__cvta_generic_to_shared(p);
}

__device__ __forceinline__ void cp16(uint32_t dst, const void* src) {
    asm volatile("cp.async.cg.shared.global [%0], [%1], 16;"
                 :: "r"(dst), "l"(src) : "memory");
}

// ---------------------------------------------------------------------------
// Kernel 1: dots[p][e] = sum_d emb[e][d] * ev[p][d]
// 1024 CTAs x 256 threads, one warp per edge (fastest measured variant).
// ---------------------------------------------------------------------------
__global__ __launch_bounds__(256) void edge_dot_kernel(
        const float* __restrict__ emb, const float* __restrict__ ev) {
    const int lane = threadIdx.x & 31;
    const int e    = (blockIdx.x * 256 + threadIdx.x) >> 5;

    float4 a = __ldg(((const float4*)emb) + e * (DIM / 4) + lane);

    float4 evr[PMAX];
#pragma unroll
    for (int p = 0; p < PMAX; ++p)
        evr[p] = __ldg(((const float4*)ev) + p * (DIM / 4) + lane);

    float part[PMAX];
#pragma unroll
    for (int p = 0; p < PMAX; ++p)
        part[p] = a.x * evr[p].x + a.y * evr[p].y +
                  a.z * evr[p].z + a.w * evr[p].w;

#pragma unroll
    for (int off = 16; off > 0; off >>= 1) {
#pragma unroll
        for (int p = 0; p < PMAX; ++p)
            part[p] += __shfl_xor_sync(0xffffffffu, part[p], off);
    }

    if (lane == 0) {
#pragma unroll
        for (int p = 0; p < PMAX; ++p)
            g_dots[p * NE + e] = part[p];
    }
}

// ---------------------------------------------------------------------------
// Kernel 2: 128 CTAs x 1024 threads x 2 pairs = 262144 exactly.
// All smem fills via distributed cp.async.cg (16B per op, all threads):
//   group 0       = paths slice (40KB, ~3 ops/thread)
//   groups 1..5   = dots p-chunks (32KB each, 2 ops/thread)
// Per-chunk wait_group + barrier pipelines gather against the fill.
// ---------------------------------------------------------------------------
__global__ __launch_bounds__(THREADS, 1) void gather_kernel(
        const int* __restrict__ paths, float* __restrict__ out) {
    extern __shared__ __align__(16) char smem[];
    float* s_dots  = (float*)smem;                 // 163840 B, [p][e]
    int*   s_paths = (int*)(smem + TBL_BYTES);     // 40960 B

    const int tid = threadIdx.x;

    // ---- group 0: paths slice (2560 x 16B ops across 1024 threads) ----
    {
        const char* src = (const char*)paths + blockIdx.x * PATH_BYTES;
        uint32_t    dst = smem_u32(s_paths);
        cp16(dst + tid * 16,          src + tid * 16);
        cp16(dst + (tid + 1024) * 16, src + (tid + 1024) * 16);
        if (tid < 512)
            cp16(dst + (tid + 2048) * 16, src + (tid + 2048) * 16);
        asm volatile("cp.async.commit_group;" ::: "memory");
    }

    // ---- groups 1..5: dots table, one p-chunk per group (2 ops/thread) ----
#pragma unroll
    for (int p = 0; p < PMAX; ++p) {
        const char* src = (const char*)g_dots + p * CHUNK_BYTES;
        uint32_t    dst = smem_u32(s_dots) + p * CHUNK_BYTES;
        cp16(dst + tid * 16,          src + tid * 16);
        cp16(dst + (tid + 1024) * 16, src + (tid + 1024) * 16);
        asm volatile("cp.async.commit_group;" ::: "memory");
    }

    // ---- paths ready: own ops done + barrier for everyone else's ----
    asm volatile("cp.async.wait_group 5;" ::: "memory");
    __syncthreads();

    // indices: thread t -> pairs t and t+1024; stride-5 = conflict-free
    int e0[PMAX], e1[PMAX];
#pragma unroll
    for (int p = 0; p < PMAX; ++p) e0[p] = s_paths[5 * tid + p];
#pragma unroll
    for (int p = 0; p < PMAX; ++p) e1[p] = s_paths[5 * (tid + 1024) + p];

    int c0 = 0, c1 = 0;
#pragma unroll
    for (int p = 0; p < PMAX; ++p) { if (e0[p] >= 0) ++c0; if (e1[p] >= 0) ++c1; }

    // ---- pipelined gather: consume each p-chunk as it completes ----
    float a0 = 0.f, a1 = 0.f;
#pragma unroll
    for (int p = 0; p < PMAX; ++p) {
        switch (p) {   // wait_group needs an immediate
            case 0: asm volatile("cp.async.wait_group 4;" ::: "memory"); break;
            case 1: asm volatile("cp.async.wait_group 3;" ::: "memory"); break;
            case 2: asm volatile("cp.async.wait_group 2;" ::: "memory"); break;
            case 3: asm volatile("cp.async.wait_group 1;" ::: "memory"); break;
            case 4: asm volatile("cp.async.wait_group 0;" ::: "memory"); break;
        }
        __syncthreads();
        const float* tp = s_dots + p * NE;
        if (e0[p] >= 0) a0 += tp[e0[p]];
        if (e1[p] >= 0) a1 += tp[e1[p]];
    }

    float* ob = out + blockIdx.x * PAIRS_CTA;
    ob[tid]        = c0 ? a0 / (float)c0 : 0.0f;
    ob[tid + 1024] = c1 ? a1 / (float)c1 : 0.0f;
}

// ---------------------------------------------------------------------------
// Launch
// ---------------------------------------------------------------------------
extern "C" void kernel_launch(void* const* d_in, const int* in_sizes, int n_in,
                              void* d_out, int out_size) {
    const float* emb   = nullptr;
    const int*   paths = nullptr;
    const float* ev    = nullptr;
    for (int i = 0; i < n_in; ++i) {
        if (in_sizes[i] == NE * DIM)                  emb   = (const float*)d_in[i];
        else if (in_sizes[i] == NNODE * NNODE * PMAX) paths = (const int*)d_in[i];
        else if (in_sizes[i] == PMAX * DIM)           ev    = (const float*)d_in[i];
    }
    float* out = (float*)d_out;

    edge_dot_kernel<<<NE / 8, 256>>>(emb, ev);

    cudaFuncSetAttribute(gather_kernel,
                         cudaFuncAttributeMaxDynamicSharedMemorySize,
                         SMEM_BYTES);
    gather_kernel<<<G_CTAS, THREADS, SMEM_BYTES>>>(paths, out);
}

// round 14
// speedup vs baseline: 1.3780x; 1.0208x over previous
#include <cuda_runtime.h>
#include <cstdint>

#define NE    8192
#define DIM   128
#define PMAX  5
#define NNODE 512
#define TOTAL (NNODE * NNODE)

#define G_CTAS       128
#define THREADS      1024
#define PAIRS_CTA    (TOTAL / G_CTAS)          // 2048
#define TBL_BYTES    (PMAX * NE * 4)           // 163840, layout [p][e]
#define CHUNK_BYTES  (NE * 4)                  // 32768 (one p slice)
#define PATH_BYTES   (PAIRS_CTA * PMAX * 4)    // 40960
#define SMEM_BYTES   (TBL_BYTES + PATH_BYTES)  // 204800

// Precomputed dot products, layout [p][e].
__device__ float g_dots[PMAX * NE];

__device__ __forceinline__ uint32_t smem_u32(const void* p) {
    return (uint32_t)__cvta_generic_to_shared(p);
}

__device__ __forceinline__ void cp16(uint32_t dst, const void* src) {
    asm volatile("cp.async.cg.shared.global [%0], [%1], 16;"
                 :: "r"(dst), "l"(src) : "memory");
}

// ---------------------------------------------------------------------------
// Kernel 1: dots[p][e] = sum_d emb[e][d] * ev[p][d]
// 1024 CTAs x 256 threads, one warp per edge (fastest measured variant).
// Carveout forced to 100% smem so the following gather kernel (200KB smem)
// needs NO per-SM L1/SMEM reconfiguration at the kernel boundary.
// ---------------------------------------------------------------------------
__global__ __launch_bounds__(256) void edge_dot_kernel(
        const float* __restrict__ emb, const float* __restrict__ ev) {
    const int lane = threadIdx.x & 31;
    const int e    = (blockIdx.x * 256 + threadIdx.x) >> 5;

    float4 a = __ldg(((const float4*)emb) + e * (DIM / 4) + lane);

    float4 evr[PMAX];
#pragma unroll
    for (int p = 0; p < PMAX; ++p)
        evr[p] = __ldg(((const float4*)ev) + p * (DIM / 4) + lane);

    float part[PMAX];
#pragma unroll
    for (int p = 0; p < PMAX; ++p)
        part[p] = a.x * evr[p].x + a.y * evr[p].y +
                  a.z * evr[p].z + a.w * evr[p].w;

#pragma unroll
    for (int off = 16; off > 0; off >>= 1) {
#pragma unroll
        for (int p = 0; p < PMAX; ++p)
            part[p] += __shfl_xor_sync(0xffffffffu, part[p], off);
    }

    if (lane == 0) {
#pragma unroll
        for (int p = 0; p < PMAX; ++p)
            g_dots[p * NE + e] = part[p];
    }
}

// ---------------------------------------------------------------------------
// Kernel 2: 128 CTAs x 1024 threads x 2 pairs = 262144 exactly.
// All smem fills via distributed cp.async.cg (16B per op, all threads):
//   group 0       = paths slice (40KB, ~3 ops/thread)
//   groups 1..5   = dots p-chunks (32KB each, 2 ops/thread)
// Per-chunk wait_group + barrier pipelines gather against the fill.
// ---------------------------------------------------------------------------
__global__ __launch_bounds__(THREADS, 1) void gather_kernel(
        const int* __restrict__ paths, float* __restrict__ out) {
    extern __shared__ __align__(16) char smem[];
    float* s_dots  = (float*)smem;                 // 163840 B, [p][e]
    int*   s_paths = (int*)(smem + TBL_BYTES);     // 40960 B

    const int tid = threadIdx.x;

    // ---- group 0: paths slice (2560 x 16B ops across 1024 threads) ----
    {
        const char* src = (const char*)paths + blockIdx.x * PATH_BYTES;
        uint32_t    dst = smem_u32(s_paths);
        cp16(dst + tid * 16,          src + tid * 16);
        cp16(dst + (tid + 1024) * 16, src + (tid + 1024) * 16);
        if (tid < 512)
            cp16(dst + (tid + 2048) * 16, src + (tid + 2048) * 16);
        asm volatile("cp.async.commit_group;" ::: "memory");
    }

    // ---- groups 1..5: dots table, one p-chunk per group (2 ops/thread) ----
#pragma unroll
    for (int p = 0; p < PMAX; ++p) {
        const char* src = (const char*)g_dots + p * CHUNK_BYTES;
        uint32_t    dst = smem_u32(s_dots) + p * CHUNK_BYTES;
        cp16(dst + tid * 16,          src + tid * 16);
        cp16(dst + (tid + 1024) * 16, src + (tid + 1024) * 16);
        asm volatile("cp.async.commit_group;" ::: "memory");
    }

    // ---- paths ready: own ops done + barrier for everyone else's ----
    asm volatile("cp.async.wait_group 5;" ::: "memory");
    __syncthreads();

    // indices: thread t -> pairs t and t+1024; stride-5 = conflict-free
    int e0[PMAX], e1[PMAX];
#pragma unroll
    for (int p = 0; p < PMAX; ++p) e0[p] = s_paths[5 * tid + p];
#pragma unroll
    for (int p = 0; p < PMAX; ++p) e1[p] = s_paths[5 * (tid + 1024) + p];

    int c0 = 0, c1 = 0;
#pragma unroll
    for (int p = 0; p < PMAX; ++p) { if (e0[p] >= 0) ++c0; if (e1[p] >= 0) ++c1; }

    // ---- pipelined gather: consume each p-chunk as it completes ----
    float a0 = 0.f, a1 = 0.f;
#pragma unroll
    for (int p = 0; p < PMAX; ++p) {
        switch (p) {   // wait_group needs an immediate
            case 0: asm volatile("cp.async.wait_group 4;" ::: "memory"); break;
            case 1: asm volatile("cp.async.wait_group 3;" ::: "memory"); break;
            case 2: asm volatile("cp.async.wait_group 2;" ::: "memory"); break;
            case 3: asm volatile("cp.async.wait_group 1;" ::: "memory"); break;
            case 4: asm volatile("cp.async.wait_group 0;" ::: "memory"); break;
        }
        __syncthreads();
        const float* tp = s_dots + p * NE;
        if (e0[p] >= 0) a0 += tp[e0[p]];
        if (e1[p] >= 0) a1 += tp[e1[p]];
    }

    float* ob = out + blockIdx.x * PAIRS_CTA;
    ob[tid]        = c0 ? a0 / (float)c0 : 0.0f;
    ob[tid + 1024] = c1 ? a1 / (float)c1 : 0.0f;
}

// ---------------------------------------------------------------------------
// Launch
// ---------------------------------------------------------------------------
extern "C" void kernel_launch(void* const* d_in, const int* in_sizes, int n_in,
                              void* d_out, int out_size) {
    const float* emb   = nullptr;
    const int*   paths = nullptr;
    const float* ev    = nullptr;
    for (int i = 0; i < n_in; ++i) {
        if (in_sizes[i] == NE * DIM)                  emb   = (const float*)d_in[i];
        else if (in_sizes[i] == NNODE * NNODE * PMAX) paths = (const int*)d_in[i];
        else if (in_sizes[i] == PMAX * DIM)           ev    = (const float*)d_in[i];
    }
    float* out = (float*)d_out;

    // Avoid per-SM L1/SMEM carveout reconfiguration between the two kernels:
    // run the dot kernel under the same max-smem carveout the gather needs.
    cudaFuncSetAttribute(edge_dot_kernel,
                         cudaFuncAttributePreferredSharedMemoryCarveout, 100);

    edge_dot_kernel<<<NE / 8, 256>>>(emb, ev);

    cudaFuncSetAttribute(gather_kernel,
                         cudaFuncAttributeMaxDynamicSharedMemorySize,
                         SMEM_BYTES);
    gather_kernel<<<G_CTAS, THREADS, SMEM_BYTES>>>(paths, out);
}